// round 11
// baseline (speedup 1.0000x reference)
#include <cuda_runtime.h>
#include <cuda_bf16.h>
#include <cstdint>

// Shapes (fixed)
#define Bb  4
#define Qq  100
#define Cc  81
#define Mm  50
#define HWN 65536

// Tiling
#define SPL 36            // K-splits per batch; grid = 36 x 4 = 144 CTAs (1 wave)
#define KC  64            // k-elements per stage
#define PW2 52            // padded m-width in scratch

// bf16 tiles: rows stride 144B -> conflict-free ldmatrix
#define RS     144
#define SS_OFF (128 * RS)
#define TS_OFF (2 * 128 * RS)
#define STAGE  (2 * 128 * RS + 64 * RS)  // 46080
#define SMEM_BYTES (2 * STAGE)           // 92160

// -------- device scratch (static; no allocations) --------
__device__ float g_px[(size_t)Bb * Qq * SPL * PW2];  // x.t partials
__device__ float g_ps[(size_t)Bb * Qq * SPL * PW2];  // tanh(x/2).t partials
__device__ float g_spp[Bb * Qq * SPL];               // softplus row partials
__device__ float g_sgp[Bb * Qq * SPL];               // tanh row partials
__device__ float g_tsp[Bb * SPL * Mm];               // t row partials

__device__ __forceinline__ uint32_t s2u(const void* p) {
    uint32_t a;
    asm("{ .reg .u64 t; cvta.to.shared.u64 t, %1; cvt.u32.u64 %0, t; }" : "=r"(a) : "l"(p));
    return a;
}
__device__ __forceinline__ void ldsm4(uint32_t* r, uint32_t a) {
    asm volatile("ldmatrix.sync.aligned.m8n8.x4.shared.b16 {%0,%1,%2,%3}, [%4];"
                 : "=r"(r[0]), "=r"(r[1]), "=r"(r[2]), "=r"(r[3]) : "r"(a));
}
__device__ __forceinline__ void mma16816(float* c, const uint32_t* a, uint32_t b0, uint32_t b1) {
    asm volatile("mma.sync.aligned.m16n8k16.row.col.f32.bf16.bf16.f32 "
                 "{%0,%1,%2,%3}, {%4,%5,%6,%7}, {%8,%9}, {%0,%1,%2,%3};"
                 : "+f"(c[0]), "+f"(c[1]), "+f"(c[2]), "+f"(c[3])
                 : "r"(a[0]), "r"(a[1]), "r"(a[2]), "r"(a[3]), "r"(b0), "r"(b1));
}

// ============ warp-specialized convert/mma kernel ============
// warps 0-3: producers (LDG fp32 -> convert -> STS bf16), one per SMSP
// warps 4-7: consumers (ldsm + mma, accumulators),        one per SMSP
__global__ __launch_bounds__(256, 1)
void cost_main(const float* __restrict__ X, const float* __restrict__ T) {
    extern __shared__ char smem[];
    const uint32_t sm0 = s2u(smem);

    const int tid = threadIdx.x;
    const int l   = tid & 31;
    const int wid = tid >> 5;
    const bool producer = (wid < 4);

    const int split = blockIdx.x;
    const int b     = blockIdx.y;
    const int nst   = (split < 16) ? 29 : 28;
    const int k0    = (split * 28 + min(split, 16)) * KC;

    const float* Xb = X + (size_t)b * Qq * HWN;
    const float* Tb = T + (size_t)b * Mm * HWN;

    // ---------------- producer state ----------------
    const int rb2 = tid >> 4;          // 0..7 (producer tids 0..127)
    const int cg  = tid & 15;          // 0..15 column group (4 floats)
    float4 rx[13], rt[7];
    float xa[13], ta[13], la[13], ts[7];
#pragma unroll
    for (int i = 0; i < 13; i++) { xa[i] = 0.f; ta[i] = 0.f; la[i] = 0.f; }
#pragma unroll
    for (int i = 0; i < 7; i++) ts[i] = 0.f;

    // ---------------- consumer state ----------------
    const int cwid = wid - 4;                          // 0..3
    const int a0   = (cwid & 1) ? 4 : 0;               // first m16 tile
    const int na   = (cwid & 1) ? 3 : 4;               // m16 tile count
    const bool isX = (cwid < 2);                       // x vs tanh matrix
    // ldmatrix lane addresses
    uint32_t aAddr[4], bAddr[4];
#pragma unroll
    for (int ia = 0; ia < 4; ia++)
        aAddr[ia] = sm0 + (isX ? 0u : (uint32_t)SS_OFF) +
                    (uint32_t)((a0 + ia) * 16 + (l & 15)) * RS + ((l >> 4) & 1) * 16;
#pragma unroll
    for (int bt = 0; bt < 4; bt++)
        bAddr[bt] = sm0 + TS_OFF +
                    (uint32_t)(bt * 16 + (l & 7) + ((l >> 4) & 1) * 8) * RS + ((l >> 3) & 1) * 16;

    float acc[4][7][4];
#pragma unroll
    for (int ia = 0; ia < 4; ia++)
#pragma unroll
        for (int n8 = 0; n8 < 7; n8++)
#pragma unroll
            for (int r = 0; r < 4; r++) acc[ia][n8][r] = 0.f;

    // ---------------- prologue: producers stage 0 loads ----------------
    if (producer) {
        const int kg = k0 + 4 * cg;
#pragma unroll
        for (int i = 0; i < 13; i++) {
            const int r = rb2 + 8 * i;
            if (r < Qq) rx[i] = *(const float4*)(Xb + (size_t)r * HWN + kg);
        }
#pragma unroll
        for (int i = 0; i < 7; i++) {
            const int r = rb2 + 8 * i;
            if (r < Mm) rt[i] = *(const float4*)(Tb + (size_t)r * HWN + kg);
        }
    }

    // ---------------- pipeline: nst+1 iterations ----------------
    for (int k = 0; k <= nst; k++) {
        if (producer) {
            if (k < nst) {
                char* const bufp = smem + (k & 1) * STAGE;
                const bool more = (k + 1 < nst);
                const int kg = k0 + (k + 1) * KC + 4 * cg;
#pragma unroll
                for (int i = 0; i < 13; i++) {
                    const int r = rb2 + 8 * i;
                    if (r < Qq) {
                        const float4 v = rx[i];
                        if (more) rx[i] = *(const float4*)(Xb + (size_t)r * HWN + kg);
                        const float xs[4] = {v.x, v.y, v.z, v.w};
                        float tv[4];
#pragma unroll
                        for (int j = 0; j < 4; j++) {
                            const float xx = xs[j];
                            float th;
                            asm("tanh.approx.f32 %0, %1;" : "=f"(th) : "f"(0.5f * xx));
                            tv[j] = th;
                            float lg;
                            asm("lg2.approx.f32 %0, %1;" : "=f"(lg) : "f"(fmaf(0.5f, th, 0.5f)));
                            xa[i] += xx; ta[i] += th; la[i] += lg;
                        }
                        __nv_bfloat162 hx0 = __float22bfloat162_rn(make_float2(xs[0], xs[1]));
                        __nv_bfloat162 hx1 = __float22bfloat162_rn(make_float2(xs[2], xs[3]));
                        __nv_bfloat162 ht0 = __float22bfloat162_rn(make_float2(tv[0], tv[1]));
                        __nv_bfloat162 ht1 = __float22bfloat162_rn(make_float2(tv[2], tv[3]));
                        char* const p = bufp + r * RS + cg * 8;
                        *reinterpret_cast<uint2*>(p) =
                            make_uint2(*reinterpret_cast<uint32_t*>(&hx0), *reinterpret_cast<uint32_t*>(&hx1));
                        *reinterpret_cast<uint2*>(p + SS_OFF) =
                            make_uint2(*reinterpret_cast<uint32_t*>(&ht0), *reinterpret_cast<uint32_t*>(&ht1));
                    }
                }
#pragma unroll
                for (int i = 0; i < 7; i++) {
                    const int r = rb2 + 8 * i;
                    if (r < Mm) {
                        const float4 w = rt[i];
                        if (more) rt[i] = *(const float4*)(Tb + (size_t)r * HWN + kg);
                        ts[i] += w.x + w.y + w.z + w.w;
                        __nv_bfloat162 h0 = __float22bfloat162_rn(make_float2(w.x, w.y));
                        __nv_bfloat162 h1 = __float22bfloat162_rn(make_float2(w.z, w.w));
                        *reinterpret_cast<uint2*>(bufp + TS_OFF + r * RS + cg * 8) =
                            make_uint2(*reinterpret_cast<uint32_t*>(&h0), *reinterpret_cast<uint32_t*>(&h1));
                    }
                }
            }
        } else {
            if (k >= 1) {
                // mma stage k-1 from buf (k-1)&1
                const uint32_t boff = (uint32_t)((k - 1) & 1) * STAGE;
#pragma unroll
                for (int st = 0; st < 4; st++) {
                    const uint32_t so = boff + st * 32;
                    uint32_t af[4][4], bf[4][4];
#pragma unroll
                    for (int ia = 0; ia < 4; ia++)
                        if (ia < na) ldsm4(af[ia], aAddr[ia] + so);
#pragma unroll
                    for (int bt = 0; bt < 4; bt++) ldsm4(bf[bt], bAddr[bt] + so);
#pragma unroll
                    for (int ia = 0; ia < 4; ia++) {
                        if (ia < na) {
#pragma unroll
                            for (int n8 = 0; n8 < 7; n8++)
                                mma16816(acc[ia][n8], af[ia],
                                         bf[n8 >> 1][(n8 & 1) * 2],
                                         bf[n8 >> 1][(n8 & 1) * 2 + 1]);
                        }
                    }
                }
            }
        }
        __syncthreads();
        // safety: convert(k+1) writes buf (k+1)&1 = (k-1)&1, which consumers
        // finished reading (stage k-1) before this barrier.
    }

    // ---------------- epilogue ----------------
    if (producer) {
        // row stats: 16 lanes share a row
#pragma unroll
        for (int i = 0; i < 13; i++) {
            float v1 = xa[i], v2 = ta[i], v3 = la[i];
#pragma unroll
            for (int off = 8; off; off >>= 1) {
                v1 += __shfl_down_sync(0xffffffffu, v1, off, 16);
                v2 += __shfl_down_sync(0xffffffffu, v2, off, 16);
                v3 += __shfl_down_sync(0xffffffffu, v3, off, 16);
            }
            const int r = rb2 + 8 * i;
            if (cg == 0 && r < Qq) {
                g_spp[(b * Qq + r) * SPL + split] = v1 - 0.69314718f * v3;   // softplus
                g_sgp[(b * Qq + r) * SPL + split] = v2;                      // sum tanh
            }
        }
#pragma unroll
        for (int i = 0; i < 7; i++) {
            float v = ts[i];
#pragma unroll
            for (int off = 8; off; off >>= 1) v += __shfl_down_sync(0xffffffffu, v, off, 16);
            const int r = rb2 + 8 * i;
            if (cg == 0 && r < Mm) g_tsp[(b * SPL + split) * Mm + r] = v;
        }
    } else {
        float* const dst = isX ? g_px : g_ps;
        const int ql = l >> 2;
        const int mo = 2 * (l & 3);
#pragma unroll
        for (int ia = 0; ia < 4; ia++) {
            if (ia < na) {
                const int qb = (a0 + ia) * 16;
#pragma unroll
                for (int n8 = 0; n8 < 7; n8++) {
                    const int m = n8 * 8 + mo;
                    if (m < Mm) {
                        const int q = qb + ql;
                        if (q < Qq) {
                            const size_t idx = ((size_t)(b * Qq + q) * SPL + split) * PW2 + m;
                            *(float2*)&dst[idx] = make_float2(acc[ia][n8][0], acc[ia][n8][1]);
                        }
                        if (q + 8 < Qq) {
                            const size_t idx = ((size_t)(b * Qq + q + 8) * SPL + split) * PW2 + m;
                            *(float2*)&dst[idx] = make_float2(acc[ia][n8][2], acc[ia][n8][3]);
                        }
                    }
                }
            }
        }
    }
}

// ================= finalize: coalesced reduce + softmax + assemble =================
// g_ps holds tanh-dot; sig.t = 0.5*tanh_dot + 0.5*Sum(t)
__global__ __launch_bounds__(512)
void finalize_k(const float* __restrict__ logits,
                const unsigned int* __restrict__ ids,
                float* __restrict__ out) {
    const int bq = blockIdx.x;           // 0..B*Q-1
    const int b  = bq / Qq;
    const int tid = threadIdx.x;
    __shared__ float se[Cc];
    __shared__ __align__(16) float sx[SPL][PW2];
    __shared__ __align__(16) float ss_[SPL][PW2];
    __shared__ float spv[SPL], sgv[SPL];
    __shared__ float sinv, ssp, ssg;
    __shared__ int s64;

    if (tid == 0) s64 = 1;
    if (tid < Cc) se[tid] = logits[bq * Cc + tid];
    if (tid < 100 && ids[2 * tid + 1] != 0u) s64 = 0;   // int64 high words all zero

    if (tid < SPL * 13) {
        const int s = tid / 13, c = (tid % 13) * 4;
        const size_t base = ((size_t)bq * SPL + s) * PW2 + c;
        *(float4*)&sx[s][c]  = *(const float4*)&g_px[base];
        *(float4*)&ss_[s][c] = *(const float4*)&g_ps[base];
    }
    if (tid >= 468 && tid < 468 + SPL) {
        const int s = tid - 468;
        spv[s] = g_spp[(size_t)bq * SPL + s];
        sgv[s] = g_sgp[(size_t)bq * SPL + s];
    }
    __syncthreads();

    if (tid < 32) {
        float mx = -1e30f;
        for (int c = tid; c < Cc; c += 32) mx = fmaxf(mx, se[c]);
#pragma unroll
        for (int off = 16; off; off >>= 1) mx = fmaxf(mx, __shfl_xor_sync(0xffffffffu, mx, off));
        float sm = 0.f;
        for (int c = tid; c < Cc; c += 32) { const float e = __expf(se[c] - mx); se[c] = e; sm += e; }
#pragma unroll
        for (int off = 16; off; off >>= 1) sm += __shfl_xor_sync(0xffffffffu, sm, off);
        if (tid == 0) sinv = __fdividef(1.0f, sm);
    }
    if (tid == 62) { float v = 0.f; for (int s = 0; s < SPL; s++) v += spv[s]; ssp = v; }
    if (tid == 63) { float v = 0.f; for (int s = 0; s < SPL; s++) v += sgv[s]; ssg = v; }

    float ax = 0.f, ath = 0.f, at = 0.f;
    if (tid < Mm) {
#pragma unroll
        for (int s = 0; s < SPL; s++) {
            ax  += sx[s][tid];
            ath += ss_[s][tid];
            at  += g_tsp[(b * SPL + s) * Mm + tid];
        }
    }
    __syncthreads();

    if (tid < Mm) {
        const int m = tid;
        const unsigned id = s64 ? ids[2 * (b * Mm + m)] : ids[b * Mm + m];
        const float prob    = se[id] * sinv;
        const float spm     = ssp * (1.0f / (float)HWN);
        const float sig_dot = fmaf(0.5f, ath, 0.5f * at);               // sig(x).t
        const float sig_sum = fmaf(0.5f, ssg, 0.5f * (float)HWN);       // sum sig
        const float denom   = sig_sum + at + 1e-6f;
        out[bq * Mm + m] = -prob + (spm - ax * (1.0f / (float)HWN)) + 1.0f - 2.0f * sig_dot / denom;
    }
}

extern "C" void kernel_launch(void* const* d_in, const int* in_sizes, int n_in,
                              void* d_out, int out_size) {
    const float*        logits = (const float*)d_in[0];        // [B,Q,C]
    const float*        pmask  = (const float*)d_in[1];        // [B,Q,H,W]
    const unsigned int* ids    = (const unsigned int*)d_in[2]; // [B,M] int32 or int64
    const float*        tmask  = (const float*)d_in[3];        // [B,M,H,W]
    float*              out    = (float*)d_out;                // [B,Q,M]

    cudaFuncSetAttribute(cost_main, cudaFuncAttributeMaxDynamicSharedMemorySize, SMEM_BYTES);
    dim3 grid(SPL, Bb);
    cost_main<<<grid, 256, SMEM_BYTES>>>(pmask, tmask);
    finalize_k<<<Bb * Qq, 512>>>(logits, ids, out);
}

// round 12
// speedup vs baseline: 2.6532x; 2.6532x over previous
#include <cuda_runtime.h>
#include <cuda_bf16.h>
#include <cstdint>

// Shapes (fixed)
#define Bb  4
#define Qq  100
#define Cc  81
#define Mm  50
#define HWN 65536

// Tiling
#define SPL 36            // K-splits per batch; grid = 36 x 4 = 144 CTAs (1 wave)
#define KC  64            // k-elements per stage

// bf16 tiles: rows stride 144B -> conflict-free ldmatrix
#define RS     144
#define SS_OFF (128 * RS)
#define TS_OFF (2 * 128 * RS)
#define STAGE  (2 * 128 * RS + 64 * RS)  // 46080
#define SMEM_BYTES (2 * STAGE)           // 92160

// -------- device scratch (static; zero-initialized at load) --------
// Accumulators are atomically summed by cost_main and RE-ZEROED by the
// finalize block that owns them, so every launch starts from zeros.
__device__ float g_ax [Bb * Qq * Mm];   // x.t
__device__ float g_ath[Bb * Qq * Mm];   // tanh(x/2).t
__device__ float g_sp [Bb * Qq];        // softplus row sums
__device__ float g_th [Bb * Qq];        // tanh row sums
__device__ float g_tsp[Bb * SPL * Mm];  // t row sums per split (overwritten, no zeroing)

__device__ __forceinline__ uint32_t s2u(const void* p) {
    uint32_t a;
    asm("{ .reg .u64 t; cvta.to.shared.u64 t, %1; cvt.u32.u64 %0, t; }" : "=r"(a) : "l"(p));
    return a;
}
__device__ __forceinline__ void ldsm4(uint32_t* r, uint32_t a) {
    asm volatile("ldmatrix.sync.aligned.m8n8.x4.shared.b16 {%0,%1,%2,%3}, [%4];"
                 : "=r"(r[0]), "=r"(r[1]), "=r"(r[2]), "=r"(r[3]) : "r"(a));
}
__device__ __forceinline__ void mma16816(float* c, const uint32_t* a, uint32_t b0, uint32_t b1) {
    asm volatile("mma.sync.aligned.m16n8k16.row.col.f32.bf16.bf16.f32 "
                 "{%0,%1,%2,%3}, {%4,%5,%6,%7}, {%8,%9}, {%0,%1,%2,%3};"
                 : "+f"(c[0]), "+f"(c[1]), "+f"(c[2]), "+f"(c[3])
                 : "r"(a[0]), "r"(a[1]), "r"(a[2]), "r"(a[3]), "r"(b0), "r"(b1));
}

// ================= fused convert + dual bf16 mma.sync GEMM (R7 core) =================
__global__ __launch_bounds__(256, 1)
void cost_main(const float* __restrict__ X, const float* __restrict__ T) {
    extern __shared__ char smem[];
    const uint32_t sm0 = s2u(smem);

    const int tid = threadIdx.x;
    const int l   = tid & 31;
    const int wid = tid >> 5;
    const int wr  = wid >> 1;          // warp row 0..3 (32 q-rows each)
    const int wc  = wid & 1;           // warp col 0..1 (n-cols 0-31 / 32-55)
    const int rb  = tid >> 4;          // 0..15 load row
    const int cg  = tid & 15;          // 0..15 column group (4 floats)
    const int nt  = wc ? 3 : 4;        // n8 tiles (cols >= 56 skipped)

    const int split = blockIdx.x;
    const int b     = blockIdx.y;
    const int nst   = (split < 16) ? 29 : 28;
    const int k0    = (split * 28 + min(split, 16)) * KC;

    const float* Xb = X + (size_t)b * Qq * HWN;
    const float* Tb = T + (size_t)b * Mm * HWN;

    // ldmatrix per-lane base addresses (canonical m8n8.x4 patterns)
    const uint32_t sA0 = sm0 + (uint32_t)(wr * 32 + (l & 15)) * RS + ((l >> 4) & 1) * 16;
    const uint32_t sA1 = sA0 + 16 * RS;
    const uint32_t sS0 = sA0 + SS_OFF;
    const uint32_t sS1 = sA1 + SS_OFF;
    const uint32_t sB0 = sm0 + TS_OFF +
        (uint32_t)(wc * 32 + (l & 7) + ((l >> 4) & 1) * 8) * RS + ((l >> 3) & 1) * 16;
    const uint32_t sB1 = sB0 + 16 * RS;

    float accx[2][4][4], accs[2][4][4];
#pragma unroll
    for (int i = 0; i < 2; i++)
#pragma unroll
        for (int j = 0; j < 4; j++)
#pragma unroll
            for (int k = 0; k < 4; k++) { accx[i][j][k] = 0.f; accs[i][j][k] = 0.f; }

    float xa[7] = {0,0,0,0,0,0,0};   // sum x
    float ta[7] = {0,0,0,0,0,0,0};   // sum tanh(x/2)
    float la[7] = {0,0,0,0,0,0,0};   // sum lg2(sigmoid(x))
    float ts_acc[4] = {0,0,0,0};

    float4 rx[7], rt[4];
    // prologue: prefetch stage 0 into registers
    {
        const int kg = k0 + 4 * cg;
#pragma unroll
        for (int i = 0; i < 7; i++) {
            const int r = rb + 16 * i;
            if (r < Qq) rx[i] = *(const float4*)(Xb + (size_t)r * HWN + kg);
        }
#pragma unroll
        for (int i = 0; i < 4; i++) {
            const int r = rb + 16 * i;
            if (r < Mm) rt[i] = *(const float4*)(Tb + (size_t)r * HWN + kg);
        }
    }

    for (int s = 0; s < nst; s++) {
        const int buf = s & 1;
        char* const bufp = smem + buf * STAGE;

        // ---- convert staged regs -> bf16 smem: x and tanh(x/2) ----
#pragma unroll
        for (int i = 0; i < 7; i++) {
            const int r = rb + 16 * i;
            if (r < Qq) {
                const float xs[4] = {rx[i].x, rx[i].y, rx[i].z, rx[i].w};
                float tv[4];
#pragma unroll
                for (int j = 0; j < 4; j++) {
                    const float xx = xs[j];
                    float th;
                    asm("tanh.approx.f32 %0, %1;" : "=f"(th) : "f"(0.5f * xx));
                    tv[j] = th;
                    float lg;
                    asm("lg2.approx.f32 %0, %1;" : "=f"(lg) : "f"(fmaf(0.5f, th, 0.5f)));
                    xa[i] += xx; ta[i] += th; la[i] += lg;
                }
                __nv_bfloat162 hx0 = __float22bfloat162_rn(make_float2(xs[0], xs[1]));
                __nv_bfloat162 hx1 = __float22bfloat162_rn(make_float2(xs[2], xs[3]));
                __nv_bfloat162 ht0 = __float22bfloat162_rn(make_float2(tv[0], tv[1]));
                __nv_bfloat162 ht1 = __float22bfloat162_rn(make_float2(tv[2], tv[3]));
                char* const p = bufp + r * RS + cg * 8;
                *reinterpret_cast<uint2*>(p) =
                    make_uint2(*reinterpret_cast<uint32_t*>(&hx0), *reinterpret_cast<uint32_t*>(&hx1));
                *reinterpret_cast<uint2*>(p + SS_OFF) =
                    make_uint2(*reinterpret_cast<uint32_t*>(&ht0), *reinterpret_cast<uint32_t*>(&ht1));
            }
        }
#pragma unroll
        for (int i = 0; i < 4; i++) {
            const int r = rb + 16 * i;
            if (r < Mm) {
                const float4 w = rt[i];
                ts_acc[i] += w.x + w.y + w.z + w.w;
                __nv_bfloat162 h0 = __float22bfloat162_rn(make_float2(w.x, w.y));
                __nv_bfloat162 h1 = __float22bfloat162_rn(make_float2(w.z, w.w));
                *reinterpret_cast<uint2*>(bufp + TS_OFF + r * RS + cg * 8) =
                    make_uint2(*reinterpret_cast<uint32_t*>(&h0), *reinterpret_cast<uint32_t*>(&h1));
            }
        }

        // ---- prefetch next stage (in flight across the mma phase) ----
        if (s + 1 < nst) {
            const int kg = k0 + (s + 1) * KC + 4 * cg;
#pragma unroll
            for (int i = 0; i < 7; i++) {
                const int r = rb + 16 * i;
                if (r < Qq) rx[i] = *(const float4*)(Xb + (size_t)r * HWN + kg);
            }
#pragma unroll
            for (int i = 0; i < 4; i++) {
                const int r = rb + 16 * i;
                if (r < Mm) rt[i] = *(const float4*)(Tb + (size_t)r * HWN + kg);
            }
        }

        __syncthreads();

        // ---- dual mma over KC=64 (4 k16-steps) ----
        const uint32_t boff = (uint32_t)buf * STAGE;
#pragma unroll
        for (int st = 0; st < 4; st++) {
            const uint32_t so = boff + st * 32;
            uint32_t ax0[4], ax1[4], as0[4], as1[4], bb0[4], bb1[4];
            ldsm4(ax0, sA0 + so); ldsm4(ax1, sA1 + so);
            ldsm4(as0, sS0 + so); ldsm4(as1, sS1 + so);
            ldsm4(bb0, sB0 + so); ldsm4(bb1, sB1 + so);
            const uint32_t bfr[4][2] = {{bb0[0], bb0[1]}, {bb0[2], bb0[3]},
                                        {bb1[0], bb1[1]}, {bb1[2], bb1[3]}};
#pragma unroll
            for (int fc = 0; fc < 4; fc++) {
                if (fc < nt) {
                    mma16816(accx[0][fc], ax0, bfr[fc][0], bfr[fc][1]);
                    mma16816(accs[0][fc], as0, bfr[fc][0], bfr[fc][1]);
                    mma16816(accx[1][fc], ax1, bfr[fc][0], bfr[fc][1]);
                    mma16816(accs[1][fc], as1, bfr[fc][0], bfr[fc][1]);
                }
            }
        }
        // 2-buffer, 1-sync safety: convert(s+1) writes the other buffer.
    }

    // ---- row-stat reductions (16 lanes share a row) -> atomic accumulators ----
#pragma unroll
    for (int i = 0; i < 7; i++) {
        float v1 = xa[i], v2 = ta[i], v3 = la[i];
#pragma unroll
        for (int off = 8; off; off >>= 1) {
            v1 += __shfl_down_sync(0xffffffffu, v1, off, 16);
            v2 += __shfl_down_sync(0xffffffffu, v2, off, 16);
            v3 += __shfl_down_sync(0xffffffffu, v3, off, 16);
        }
        const int r = rb + 16 * i;
        if (cg == 0 && r < Qq) {
            atomicAdd(&g_sp[b * Qq + r], v1 - 0.69314718f * v3);   // softplus
            atomicAdd(&g_th[b * Qq + r], v2);                      // sum tanh
        }
    }
#pragma unroll
    for (int i = 0; i < 4; i++) {
        float v = ts_acc[i];
#pragma unroll
        for (int off = 8; off; off >>= 1) v += __shfl_down_sync(0xffffffffu, v, off, 16);
        const int r = rb + 16 * i;
        if (cg == 0 && r < Mm) g_tsp[(b * SPL + split) * Mm + r] = v;   // per-split write
    }

    // ---- mma partials -> atomic accumulation into [B,Q,M] ----
    {
        const int ql = l >> 2;
        const int mo = 2 * (l & 3);
#pragma unroll
        for (int fr = 0; fr < 2; fr++)
#pragma unroll
            for (int fc = 0; fc < 4; fc++) {
                if (fc < nt) {
                    const int m = wc * 32 + fc * 8 + mo;   // even, m+1 <= 49 when m < Mm
                    if (m < Mm) {
                        const int q = wr * 32 + fr * 16 + ql;
                        if (q < Qq) {
                            const int idx = (b * Qq + q) * Mm + m;
                            atomicAdd(&g_ax [idx],     accx[fr][fc][0]);
                            atomicAdd(&g_ax [idx + 1], accx[fr][fc][1]);
                            atomicAdd(&g_ath[idx],     accs[fr][fc][0]);
                            atomicAdd(&g_ath[idx + 1], accs[fr][fc][1]);
                        }
                        if (q + 8 < Qq) {
                            const int idx = (b * Qq + q + 8) * Mm + m;
                            atomicAdd(&g_ax [idx],     accx[fr][fc][2]);
                            atomicAdd(&g_ax [idx + 1], accx[fr][fc][3]);
                            atomicAdd(&g_ath[idx],     accs[fr][fc][2]);
                            atomicAdd(&g_ath[idx + 1], accs[fr][fc][3]);
                        }
                    }
                }
            }
    }
}

// ================= finalize: softmax + assemble + re-zero owned accumulators =======
// g_ath holds tanh-dot; sig.t = 0.5*tanh_dot + 0.5*Sum(t)
__global__ __launch_bounds__(128)
void finalize_k(const float* __restrict__ logits,
                const unsigned int* __restrict__ ids,
                float* __restrict__ out) {
    const int bq = blockIdx.x;           // 0..B*Q-1
    const int b  = bq / Qq;
    const int tid = threadIdx.x;
    __shared__ float se[Cc];
    __shared__ float sinv;
    __shared__ int s64;

    if (tid == 0) s64 = 1;
    if (tid < Cc) se[tid] = logits[bq * Cc + tid];
    if (tid < 100 && ids[2 * tid + 1] != 0u) s64 = 0;   // int64 high words all zero
    __syncthreads();

    // warp 0: parallel softmax over 81 classes
    if (tid < 32) {
        float mx = -1e30f;
        for (int c = tid; c < Cc; c += 32) mx = fmaxf(mx, se[c]);
#pragma unroll
        for (int off = 16; off; off >>= 1) mx = fmaxf(mx, __shfl_xor_sync(0xffffffffu, mx, off));
        float sm = 0.f;
        for (int c = tid; c < Cc; c += 32) { const float e = __expf(se[c] - mx); se[c] = e; sm += e; }
#pragma unroll
        for (int off = 16; off; off >>= 1) sm += __shfl_xor_sync(0xffffffffu, sm, off);
        if (tid == 0) sinv = __fdividef(1.0f, sm);
    }

    // read accumulators into registers
    float ax = 0.f, ath = 0.f, at = 0.f, ssp = 0.f, ssg = 0.f;
    if (tid < Mm) {
        ax  = g_ax [bq * Mm + tid];
        ath = g_ath[bq * Mm + tid];
#pragma unroll
        for (int s = 0; s < SPL; s++) at += g_tsp[(b * SPL + s) * Mm + tid];
        ssp = g_sp[bq];
        ssg = g_th[bq];
    }
    __syncthreads();   // all reads of g_ax/g_ath/g_sp/g_th done before zeroing

    // re-zero owned accumulators for the next launch (graph replay invariant)
    if (tid < Mm) {
        g_ax [bq * Mm + tid] = 0.f;
        g_ath[bq * Mm + tid] = 0.f;
    }
    if (tid == 64) g_sp[bq] = 0.f;
    if (tid == 65) g_th[bq] = 0.f;

    if (tid < Mm) {
        const int m = tid;
        const unsigned id = s64 ? ids[2 * (b * Mm + m)] : ids[b * Mm + m];
        const float prob    = se[id] * sinv;
        const float spm     = ssp * (1.0f / (float)HWN);
        const float sig_dot = fmaf(0.5f, ath, 0.5f * at);               // sig(x).t
        const float sig_sum = fmaf(0.5f, ssg, 0.5f * (float)HWN);       // sum sig
        const float denom   = sig_sum + at + 1e-6f;
        out[bq * Mm + m] = -prob + (spm - ax * (1.0f / (float)HWN)) + 1.0f - 2.0f * sig_dot / denom;
    }
}

extern "C" void kernel_launch(void* const* d_in, const int* in_sizes, int n_in,
                              void* d_out, int out_size) {
    const float*        logits = (const float*)d_in[0];        // [B,Q,C]
    const float*        pmask  = (const float*)d_in[1];        // [B,Q,H,W]
    const unsigned int* ids    = (const unsigned int*)d_in[2]; // [B,M] int32 or int64
    const float*        tmask  = (const float*)d_in[3];        // [B,M,H,W]
    float*              out    = (float*)d_out;                // [B,Q,M]

    cudaFuncSetAttribute(cost_main, cudaFuncAttributeMaxDynamicSharedMemorySize, SMEM_BYTES);
    dim3 grid(SPL, Bb);
    cost_main<<<grid, 256, SMEM_BYTES>>>(pmask, tmask);
    finalize_k<<<Bb * Qq, 128>>>(logits, ids, out);
}